// round 5
// baseline (speedup 1.0000x reference)
#include <cuda_runtime.h>
#include <cuda_bf16.h>
#include <math.h>
#include <stdint.h>

// ============================================================================
// HypHawkes: attn = proj(expmap0( softmax( (proj(expmap0(q)) @ W^T) @
//                                          proj(expmap0(ctx))^T / d ) ))
// n = m = 4096, d = 1024, c = 1.0 (read generically from device).
//
// Pipeline:
//   K1: row-scale query   -> g_qs  (bf16)   [fused expmap0+project = one scalar/row]
//   K2: row-scale context -> g_cs  (bf16)
//   K3: convert W         -> g_wb  (bf16)
//   K4: GEMM1 g_q2[n,d] = g_qs @ g_wb^T          (bf16 in, fp32 acc, bf16 out)
//   K5: GEMM2 g_scores[n,m] = g_q2 @ g_cs^T      (bf16 in, fp32 acc, fp32 out)
//   K6: per-row softmax(scores/d) + expmap0/project epilogue -> d_out (fp32)
// ============================================================================

#define MAXN 4096
#define MAXD 1024

__device__ __nv_bfloat16 g_qs[MAXN * MAXD];
__device__ __nv_bfloat16 g_cs[MAXN * MAXD];
__device__ __nv_bfloat16 g_wb[MAXD * MAXD];
__device__ __nv_bfloat16 g_q2[MAXN * MAXD];
__device__ float         g_scores[(size_t)MAXN * MAXN];

#define MIN_NORM 1e-5f
#define PROJ_EPS 4e-3f

// ----------------------------------------------------------------------------
// K1/K2: per-row hyperbolic scale + fp32->bf16. One CTA (256 thr) per row.
// combined scale = min(tanh(sqrt_c * r), 1-eps) / (sqrt_c * r), r = max(||u||, 1e-5)
// ----------------------------------------------------------------------------
__global__ __launch_bounds__(256)
void scale_rows_kernel(const float* __restrict__ in, __nv_bfloat16* __restrict__ out,
                       const float* __restrict__ c, int d) {
    __shared__ float sh[8];
    const int row = blockIdx.x;
    const float* r = in + (size_t)row * d;
    float ss = 0.f;
    for (int i = threadIdx.x; i < d; i += 256) { float v = r[i]; ss = fmaf(v, v, ss); }
#pragma unroll
    for (int o = 16; o; o >>= 1) ss += __shfl_xor_sync(0xffffffffu, ss, o);
    if ((threadIdx.x & 31) == 0) sh[threadIdx.x >> 5] = ss;
    __syncthreads();
    const float tot = sh[0] + sh[1] + sh[2] + sh[3] + sh[4] + sh[5] + sh[6] + sh[7];
    const float sc = sqrtf(c[0]);
    const float rn = fmaxf(sqrtf(tot), MIN_NORM);
    const float t  = fminf(tanhf(sc * rn), 1.0f - PROJ_EPS);
    const float scale = t / (sc * rn);
    __nv_bfloat16* o = out + (size_t)row * d;
    for (int i = threadIdx.x; i < d; i += 256) o[i] = __float2bfloat16(r[i] * scale);
}

// ----------------------------------------------------------------------------
// K3: fp32 -> bf16 convert (vectorized)
// ----------------------------------------------------------------------------
__global__ __launch_bounds__(256)
void convert_w_kernel(const float4* __restrict__ in, __nv_bfloat162* __restrict__ out,
                      int n4) {
    int i = blockIdx.x * blockDim.x + threadIdx.x;
    if (i < n4) {
        float4 v = in[i];
        out[2 * i]     = __floats2bfloat162_rn(v.x, v.y);
        out[2 * i + 1] = __floats2bfloat162_rn(v.z, v.w);
    }
}

// ----------------------------------------------------------------------------
// GEMM (TN): C[M,N] = A[M,K] @ B[N,K]^T, bf16 inputs, fp32 accumulate.
// CTA tile 128x128x32, 8 warps in 2(m) x 4(n) grid, warp tile 64x32 via
// mma.sync.aligned.m16n8k16.row.col. Double-buffered smem, stride-40 padding
// (row stride 80B => fragment LDS banks (20*g + tg) mod 32 are all-distinct).
// ----------------------------------------------------------------------------
__device__ __forceinline__ void mma16816(float* c, const uint32_t* a, const uint32_t* b) {
    asm volatile(
        "mma.sync.aligned.m16n8k16.row.col.f32.bf16.bf16.f32 "
        "{%0,%1,%2,%3}, {%4,%5,%6,%7}, {%8,%9}, {%0,%1,%2,%3};\n"
        : "+f"(c[0]), "+f"(c[1]), "+f"(c[2]), "+f"(c[3])
        : "r"(a[0]), "r"(a[1]), "r"(a[2]), "r"(a[3]), "r"(b[0]), "r"(b[1]));
}

template <bool OUT_BF16>
__global__ __launch_bounds__(256, 1)
void gemm_tn_kernel(const __nv_bfloat16* __restrict__ A,
                    const __nv_bfloat16* __restrict__ B,
                    void* __restrict__ Cv, int M, int N, int K) {
    const int LDS = 40;  // smem row stride in elements (80B, 16B-aligned)
    __shared__ __nv_bfloat16 As[2][128 * LDS];
    __shared__ __nv_bfloat16 Bs[2][128 * LDS];

    const int bm = blockIdx.y * 128;
    const int bn = blockIdx.x * 128;
    const int tid  = threadIdx.x;
    const int wid  = tid >> 5;
    const int lane = tid & 31;
    const int wm = (wid & 1) * 64;   // warp m offset within CTA tile
    const int wn = (wid >> 1) * 32;  // warp n offset within CTA tile
    const int g  = lane >> 2;        // group id (0..7)
    const int tg = lane & 3;         // thread-in-group (0..3)

    float acc[4][4][4];
#pragma unroll
    for (int i = 0; i < 4; i++)
#pragma unroll
        for (int j = 0; j < 4; j++)
#pragma unroll
            for (int k = 0; k < 4; k++) acc[i][j][k] = 0.f;

    // Global staging: 512 uint4 loads per (128x32) tile per operand; each
    // thread does rows r0 and r0+64, 8 bf16 per load.
    const int r0 = tid >> 2;           // 0..63
    const int s0 = (tid & 3) * 8;      // 0,8,16,24
    const __nv_bfloat16* Ag = A + (size_t)(bm + r0) * K + s0;
    const __nv_bfloat16* Bg = B + (size_t)(bn + r0) * K + s0;
    const size_t rowstep = (size_t)64 * K;

    const int nk = K >> 5;  // K/32
    uint4 pa0, pa1, pb0, pb1;

    // prologue: tile kt=0 -> smem buf 0
    pa0 = *(const uint4*)(Ag);
    pa1 = *(const uint4*)(Ag + rowstep);
    pb0 = *(const uint4*)(Bg);
    pb1 = *(const uint4*)(Bg + rowstep);
    *(uint4*)&As[0][r0 * LDS + s0]        = pa0;
    *(uint4*)&As[0][(r0 + 64) * LDS + s0] = pa1;
    *(uint4*)&Bs[0][r0 * LDS + s0]        = pb0;
    *(uint4*)&Bs[0][(r0 + 64) * LDS + s0] = pb1;
    __syncthreads();

    for (int kt = 0; kt < nk; ++kt) {
        const int buf = kt & 1;
        if (kt + 1 < nk) {  // prefetch next tile into registers (overlaps MMAs)
            const __nv_bfloat16* a = Ag + (kt + 1) * 32;
            const __nv_bfloat16* b = Bg + (kt + 1) * 32;
            pa0 = *(const uint4*)(a);
            pa1 = *(const uint4*)(a + rowstep);
            pb0 = *(const uint4*)(b);
            pb1 = *(const uint4*)(b + rowstep);
        }
#pragma unroll
        for (int ks = 0; ks < 2; ++ks) {  // two k16 steps per 32-wide tile
            const int k0 = ks * 16;
            uint32_t af[4][4];
            uint32_t bfr[4][2];
#pragma unroll
            for (int mi = 0; mi < 4; ++mi) {
                const __nv_bfloat16* p = &As[buf][(wm + mi * 16 + g) * LDS + k0 + tg * 2];
                af[mi][0] = *(const uint32_t*)(p);
                af[mi][1] = *(const uint32_t*)(p + 8 * LDS);
                af[mi][2] = *(const uint32_t*)(p + 8);
                af[mi][3] = *(const uint32_t*)(p + 8 * LDS + 8);
            }
#pragma unroll
            for (int ni = 0; ni < 4; ++ni) {
                const __nv_bfloat16* p = &Bs[buf][(wn + ni * 8 + g) * LDS + k0 + tg * 2];
                bfr[ni][0] = *(const uint32_t*)(p);
                bfr[ni][1] = *(const uint32_t*)(p + 8);
            }
#pragma unroll
            for (int mi = 0; mi < 4; ++mi)
#pragma unroll
                for (int ni = 0; ni < 4; ++ni)
                    mma16816(acc[mi][ni], af[mi], bfr[ni]);
        }
        if (kt + 1 < nk) {
            const int nb = buf ^ 1;
            *(uint4*)&As[nb][r0 * LDS + s0]        = pa0;
            *(uint4*)&As[nb][(r0 + 64) * LDS + s0] = pa1;
            *(uint4*)&Bs[nb][r0 * LDS + s0]        = pb0;
            *(uint4*)&Bs[nb][(r0 + 64) * LDS + s0] = pb1;
        }
        __syncthreads();
    }

    // epilogue: c0/c1 at (row, col..col+1), c2/c3 at (row+8, col..col+1)
    if (OUT_BF16) {
        __nv_bfloat16* C = (__nv_bfloat16*)Cv;
#pragma unroll
        for (int mi = 0; mi < 4; ++mi) {
            const int row = bm + wm + mi * 16 + g;
#pragma unroll
            for (int ni = 0; ni < 4; ++ni) {
                const int col = bn + wn + ni * 8 + tg * 2;
                *(__nv_bfloat162*)&C[(size_t)row * N + col] =
                    __floats2bfloat162_rn(acc[mi][ni][0], acc[mi][ni][1]);
                *(__nv_bfloat162*)&C[(size_t)(row + 8) * N + col] =
                    __floats2bfloat162_rn(acc[mi][ni][2], acc[mi][ni][3]);
            }
        }
    } else {
        float* C = (float*)Cv;
#pragma unroll
        for (int mi = 0; mi < 4; ++mi) {
            const int row = bm + wm + mi * 16 + g;
#pragma unroll
            for (int ni = 0; ni < 4; ++ni) {
                const int col = bn + wn + ni * 8 + tg * 2;
                *(float2*)&C[(size_t)row * N + col] =
                    make_float2(acc[mi][ni][0], acc[mi][ni][1]);
                *(float2*)&C[(size_t)(row + 8) * N + col] =
                    make_float2(acc[mi][ni][2], acc[mi][ni][3]);
            }
        }
    }
}

// ----------------------------------------------------------------------------
// K6: per-row softmax(scores * inv_d) fused with expmap0+project epilogue.
// One CTA (256 thr) per row; m/256 <= 16 values live in registers.
// attn_i = e_i/Se ; ||attn|| = sqrt(Se2)/Se ; out_i = e_i * scale/Se.
// ----------------------------------------------------------------------------
__global__ __launch_bounds__(256)
void softmax_proj_kernel(const float* __restrict__ S, float* __restrict__ out,
                         const float* __restrict__ c, int m, float inv_d) {
    __shared__ float sh[16];
    const int row = blockIdx.x;
    const float* s = S + (size_t)row * m;
    const int cnt = m >> 8;  // m/256 (m divisible by 256, cnt <= 16)

    float v[16];
    float vmax = -3.4e38f;
    for (int i = 0; i < cnt; ++i) {
        v[i] = s[threadIdx.x + (i << 8)];
        vmax = fmaxf(vmax, v[i]);
    }
#pragma unroll
    for (int o = 16; o; o >>= 1) vmax = fmaxf(vmax, __shfl_xor_sync(0xffffffffu, vmax, o));
    if ((threadIdx.x & 31) == 0) sh[threadIdx.x >> 5] = vmax;
    __syncthreads();
    const float rmax = fmaxf(fmaxf(fmaxf(sh[0], sh[1]), fmaxf(sh[2], sh[3])),
                             fmaxf(fmaxf(sh[4], sh[5]), fmaxf(sh[6], sh[7])));
    __syncthreads();  // before sh reuse

    float es = 0.f, e2 = 0.f;
    for (int i = 0; i < cnt; ++i) {
        float e = __expf((v[i] - rmax) * inv_d);
        v[i] = e;
        es += e;
        e2 = fmaf(e, e, e2);
    }
#pragma unroll
    for (int o = 16; o; o >>= 1) {
        es += __shfl_xor_sync(0xffffffffu, es, o);
        e2 += __shfl_xor_sync(0xffffffffu, e2, o);
    }
    if ((threadIdx.x & 31) == 0) {
        sh[threadIdx.x >> 5]     = es;
        sh[8 + (threadIdx.x >> 5)] = e2;
    }
    __syncthreads();
    const float tes = sh[0] + sh[1] + sh[2] + sh[3] + sh[4] + sh[5] + sh[6] + sh[7];
    const float te2 = sh[8] + sh[9] + sh[10] + sh[11] + sh[12] + sh[13] + sh[14] + sh[15];

    const float inv = 1.f / tes;
    const float rn  = fmaxf(sqrtf(te2) * inv, MIN_NORM);
    const float sc  = sqrtf(c[0]);
    const float t   = fminf(tanhf(sc * rn), 1.0f - PROJ_EPS);
    const float scale = (t / (sc * rn)) * inv;

    float* o = out + (size_t)row * m;
    for (int i = 0; i < cnt; ++i) o[threadIdx.x + (i << 8)] = v[i] * scale;
}

// ----------------------------------------------------------------------------
// kernel_launch: inputs per metadata order: query[n,d], context[m,d], W[d,d], c[1]
// ----------------------------------------------------------------------------
extern "C" void kernel_launch(void* const* d_in, const int* in_sizes, int n_in,
                              void* d_out, int out_size) {
    const float* query   = (const float*)d_in[0];
    const float* context = (const float*)d_in[1];
    const float* W       = (const float*)d_in[2];
    const float* c       = (const float*)d_in[3];

    const int d = (int)(sqrt((double)in_sizes[2]) + 0.5);
    const int n = in_sizes[0] / d;
    const int m = in_sizes[1] / d;

    __nv_bfloat16 *qs, *cs, *wb, *q2;
    float* sco;
    cudaGetSymbolAddress((void**)&qs,  g_qs);
    cudaGetSymbolAddress((void**)&cs,  g_cs);
    cudaGetSymbolAddress((void**)&wb,  g_wb);
    cudaGetSymbolAddress((void**)&q2,  g_q2);
    cudaGetSymbolAddress((void**)&sco, g_scores);

    // K1/K2: hyperbolic row scaling -> bf16
    scale_rows_kernel<<<n, 256>>>(query, qs, c, d);
    scale_rows_kernel<<<m, 256>>>(context, cs, c, d);

    // K3: W -> bf16 (B operand of GEMM1 is W itself: (q@W^T)[i,j] = sum_k q[i,k]W[j,k])
    const int n4 = (d * d) / 4;
    convert_w_kernel<<<(n4 + 255) / 256, 256>>>((const float4*)W, (__nv_bfloat162*)wb, n4);

    // K4: q2[n,d] = qs[n,d] @ wb[d,d]^T
    gemm_tn_kernel<true><<<dim3(d / 128, n / 128), 256>>>(qs, wb, (void*)q2, n, d, d);

    // K5: scores[n,m] = q2[n,d] @ cs[m,d]^T
    gemm_tn_kernel<false><<<dim3(m / 128, n / 128), 256>>>(q2, cs, (void*)sco, n, m, d);

    // K6: softmax(scores/d) + expmap0/project -> out
    softmax_proj_kernel<<<n, 256>>>(sco, (float*)d_out, c, m, 1.0f / (float)d);
}

// round 7
// speedup vs baseline: 1.4202x; 1.4202x over previous
#include <cuda_runtime.h>
#include <cuda_bf16.h>
#include <math.h>
#include <stdint.h>

// ============================================================================
// HypHawkes (fallback-HMMA path; tcgen05 unavailable: harness lowers through
// compute_103 virtual target which rejects sm_103a-only instructions).
//
//   K1/K2: row-scale query/context (fused expmap0+project scalar) -> bf16
//   K3:    W -> bf16
//   K4:    GEMM1 q2[n,d] = qs @ wb^T      (mma.sync bf16, bf16 out)
//   K5:    GEMM2 scores[n,m] = q2 @ cs^T  (mma.sync bf16, bf16 out)
//   K6:    row softmax(scores/d) + expmap0/project -> out (fp32)
//
// GEMM: CTA tile 128x256xK, K-chunk 64, 4-stage cp.async pipeline, 8 warps
// (2m x 4n), warp tile 64x64, ldmatrix.x4 fragment loads, XOR-swizzled smem
// (conflict-free for 16B cp.async writes and LDSM reads).
// ============================================================================

#define MAXN 4096
#define MAXD 1024

__device__ __nv_bfloat16 g_qs[MAXN * MAXD];
__device__ __nv_bfloat16 g_cs[MAXN * MAXD];
__device__ __nv_bfloat16 g_wb[MAXD * MAXD];
__device__ __nv_bfloat16 g_q2[MAXN * MAXD];
__device__ __nv_bfloat16 g_scores[(size_t)MAXN * MAXN];

#define MIN_NORM 1e-5f
#define PROJ_EPS 4e-3f

// ---------------------------------------------------------------------------
// helpers
// ---------------------------------------------------------------------------
__device__ __forceinline__ uint32_t smem_u32(const void* p) {
    uint32_t a;
    asm("{ .reg .u64 t; cvta.to.shared.u64 t, %1; cvt.u32.u64 %0, t; }"
        : "=r"(a) : "l"(p));
    return a;
}
__device__ __forceinline__ void cp16(uint32_t dst, const void* src) {
    asm volatile("cp.async.cg.shared.global [%0], [%1], 16;" :: "r"(dst), "l"(src));
}
#define CP_COMMIT() asm volatile("cp.async.commit_group;" ::: "memory")
#define CP_WAIT(N)  asm volatile("cp.async.wait_group %0;" :: "n"(N) : "memory")

__device__ __forceinline__ void ldsm_x4(uint32_t* r, uint32_t addr) {
    asm volatile("ldmatrix.sync.aligned.m8n8.x4.shared.b16 {%0,%1,%2,%3}, [%4];"
                 : "=r"(r[0]), "=r"(r[1]), "=r"(r[2]), "=r"(r[3]) : "r"(addr));
}
__device__ __forceinline__ void mma16816(float* c, const uint32_t* a, const uint32_t* b) {
    asm volatile(
        "mma.sync.aligned.m16n8k16.row.col.f32.bf16.bf16.f32 "
        "{%0,%1,%2,%3}, {%4,%5,%6,%7}, {%8,%9}, {%0,%1,%2,%3};\n"
        : "+f"(c[0]), "+f"(c[1]), "+f"(c[2]), "+f"(c[3])
        : "r"(a[0]), "r"(a[1]), "r"(a[2]), "r"(a[3]), "r"(b[0]), "r"(b[1]));
}

// ---------------------------------------------------------------------------
// K1/K2: per-row hyperbolic scale + fp32->bf16
// combined scale = min(tanh(sqrt_c*r), 1-eps) / (sqrt_c*r), r = max(||u||,1e-5)
// ---------------------------------------------------------------------------
__global__ __launch_bounds__(256)
void scale_rows_kernel(const float* __restrict__ in, __nv_bfloat16* __restrict__ out,
                       const float* __restrict__ c, int d) {
    __shared__ float sh[8];
    const int row = blockIdx.x;
    const float* r = in + (size_t)row * d;
    float ss = 0.f;
    for (int i = threadIdx.x; i < d; i += 256) { float v = r[i]; ss = fmaf(v, v, ss); }
#pragma unroll
    for (int o = 16; o; o >>= 1) ss += __shfl_xor_sync(0xffffffffu, ss, o);
    if ((threadIdx.x & 31) == 0) sh[threadIdx.x >> 5] = ss;
    __syncthreads();
    const float tot = sh[0] + sh[1] + sh[2] + sh[3] + sh[4] + sh[5] + sh[6] + sh[7];
    const float sc = sqrtf(c[0]);
    const float rn = fmaxf(sqrtf(tot), MIN_NORM);
    const float t  = fminf(tanhf(sc * rn), 1.0f - PROJ_EPS);
    const float scale = t / (sc * rn);
    __nv_bfloat16* o = out + (size_t)row * d;
    for (int i = threadIdx.x; i < d; i += 256) o[i] = __float2bfloat16(r[i] * scale);
}

// ---------------------------------------------------------------------------
// K3: fp32 -> bf16 convert
// ---------------------------------------------------------------------------
__global__ __launch_bounds__(256)
void convert_w_kernel(const float4* __restrict__ in, __nv_bfloat162* __restrict__ out,
                      int n4) {
    int i = blockIdx.x * blockDim.x + threadIdx.x;
    if (i < n4) {
        float4 v = in[i];
        out[2 * i]     = __floats2bfloat162_rn(v.x, v.y);
        out[2 * i + 1] = __floats2bfloat162_rn(v.z, v.w);
    }
}

// ---------------------------------------------------------------------------
// GEMM (TN): C[M,N] = A[M,K] @ B[N,K]^T, bf16 in, fp32 acc, bf16 out.
// ---------------------------------------------------------------------------
#define BM 128
#define BN 256
#define BK 64
#define STG 4
#define A_ST (BM * BK * 2)            // 16384 B
#define B_ST (BN * BK * 2)            // 32768 B
#define B_BASE (STG * A_ST)           // 65536
#define GSMEM (B_BASE + STG * B_ST)   // 196608 = 192 KB

extern __shared__ __align__(1024) char dyn_smem[];

__global__ __launch_bounds__(256, 1)
void gemm_bf16_kernel(const __nv_bfloat16* __restrict__ A,
                      const __nv_bfloat16* __restrict__ B,
                      __nv_bfloat16* __restrict__ C, int M, int N, int K) {
    const uint32_t sb = smem_u32(dyn_smem);
    const int tid  = threadIdx.x;
    const int wid  = tid >> 5;
    const int lane = tid & 31;
    const int bm = blockIdx.y * BM;
    const int bn = blockIdx.x * BN;
    const int wm = (wid & 1) * 64;
    const int wn = (wid >> 1) * 64;
    const int NK = K / BK;

    float acc[4][8][4];
#pragma unroll
    for (int i = 0; i < 4; i++)
#pragma unroll
        for (int j = 0; j < 8; j++)
#pragma unroll
            for (int k = 0; k < 4; k++) acc[i][j][k] = 0.f;

    // ---- cp.async staging: 16B chunks; rows are 128B (64 bf16), 8 chunks/row.
    // swizzle: chunk ^= (row & 7)
    auto load_stage = [&](int j) {
        const int s = j & (STG - 1);
        const uint32_t ab = sb + s * A_ST;
        const uint32_t bb = sb + B_BASE + s * B_ST;
        const __nv_bfloat16* Aj = A + (size_t)bm * K + (size_t)j * BK;
        const __nv_bfloat16* Bj = B + (size_t)bn * K + (size_t)j * BK;
#pragma unroll
        for (int i = 0; i < 4; ++i) {               // A: 1024 chunks / 256 thr
            int cid = tid + 256 * i;
            int row = cid >> 3, seg = cid & 7;
            uint32_t off = (uint32_t)(row * 128) + (uint32_t)((seg ^ (row & 7)) * 16);
            cp16(ab + off, Aj + (size_t)row * K + seg * 8);
        }
#pragma unroll
        for (int i = 0; i < 8; ++i) {               // B: 2048 chunks / 256 thr
            int cid = tid + 256 * i;
            int row = cid >> 3, seg = cid & 7;
            uint32_t off = (uint32_t)(row * 128) + (uint32_t)((seg ^ (row & 7)) * 16);
            cp16(bb + off, Bj + (size_t)row * K + seg * 8);
        }
    };

    // prologue: stages 0..2
#pragma unroll
    for (int j = 0; j < STG - 1; ++j) { load_stage(j); CP_COMMIT(); }

    // ---- per-thread LDSM address components
    const int sub  = lane >> 3;   // 0..3 (which 8x8 matrix this thread addresses)
    const int trow = lane & 7;    // row within matrix
    // A x4: matrices (m0-7,k0-7),(m8-15,k0-7),(m0-7,k8-15),(m8-15,k8-15)
    const int a_row_l = wm + (sub & 1) * 8 + trow;   // + mi*16
    const int a_kk    = (sub >> 1) * 8;              // + k0
    // B x4: matrices (n0-7,k0-7),(n0-7,k8-15),(n8-15,k0-7),(n8-15,k8-15)
    const int b_row_l = wn + (sub >> 1) * 8 + trow;  // + pi*16
    const int b_kk    = (sub & 1) * 8;               // + k0
    const uint32_t a_sw = (uint32_t)trow << 4;       // swizzle XOR on byte[6:4]
    const uint32_t b_sw = (uint32_t)trow << 4;

    for (int kt = 0; kt < NK; ++kt) {
        CP_WAIT(2);
        __syncthreads();
        const int jn = kt + STG - 1;
        if (jn < NK) load_stage(jn);
        CP_COMMIT();

        const int s = kt & (STG - 1);
        const uint32_t abase = sb + s * A_ST;
        const uint32_t bbase = sb + B_BASE + s * B_ST;

#pragma unroll
        for (int ks = 0; ks < 4; ++ks) {
            const int k0 = ks * 16;
            uint32_t af[4][4], bf[4][4];
#pragma unroll
            for (int mi = 0; mi < 4; ++mi) {
                uint32_t col = (uint32_t)((k0 + a_kk) * 2) ^ a_sw;
                ldsm_x4(af[mi], abase + (uint32_t)((a_row_l + mi * 16) * 128) + col);
            }
#pragma unroll
            for (int pi = 0; pi < 4; ++pi) {
                uint32_t col = (uint32_t)((k0 + b_kk) * 2) ^ b_sw;
                ldsm_x4(bf[pi], bbase + (uint32_t)((b_row_l + pi * 16) * 128) + col);
            }
#pragma unroll
            for (int mi = 0; mi < 4; ++mi)
#pragma unroll
                for (int ni = 0; ni < 8; ++ni)
                    mma16816(acc[mi][ni], af[mi], &bf[ni >> 1][(ni & 1) * 2]);
        }
        __syncthreads();
    }

    // ---- epilogue: c0/c1 at (row, col..col+1), c2/c3 at (row+8, ...)
    const int g  = lane >> 2;
    const int tg = lane & 3;
#pragma unroll
    for (int mi = 0; mi < 4; ++mi) {
        const int row = bm + wm + mi * 16 + g;
#pragma unroll
        for (int ni = 0; ni < 8; ++ni) {
            const int col = bn + wn + ni * 8 + tg * 2;
            *(__nv_bfloat162*)&C[(size_t)row * N + col] =
                __floats2bfloat162_rn(acc[mi][ni][0], acc[mi][ni][1]);
            *(__nv_bfloat162*)&C[(size_t)(row + 8) * N + col] =
                __floats2bfloat162_rn(acc[mi][ni][2], acc[mi][ni][3]);
        }
    }
}

// ---------------------------------------------------------------------------
// K6: row softmax(scores * inv_d) fused with expmap0+project (bf16 scores in).
// thread t owns 16 contiguous elements [t*16, t*16+16) of its row.
// ---------------------------------------------------------------------------
__global__ __launch_bounds__(256)
void softmax_proj_kernel(const __nv_bfloat16* __restrict__ S, float* __restrict__ out,
                         const float* __restrict__ c, int m, float inv_d) {
    __shared__ float sh[16];
    const int row = blockIdx.x;
    const int tid = threadIdx.x;

    // load 16 bf16 = 2 uint4
    const uint4* sv = (const uint4*)(S + (size_t)row * m) + tid * 2;
    uint4 u0 = sv[0], u1 = sv[1];
    float v[16];
    {
        const uint32_t* w = (const uint32_t*)&u0;
#pragma unroll
        for (int i = 0; i < 4; ++i) {
            __nv_bfloat162 h = *(__nv_bfloat162*)&w[i];
            v[2 * i]     = __bfloat162float(h.x);
            v[2 * i + 1] = __bfloat162float(h.y);
        }
        const uint32_t* w2 = (const uint32_t*)&u1;
#pragma unroll
        for (int i = 0; i < 4; ++i) {
            __nv_bfloat162 h = *(__nv_bfloat162*)&w2[i];
            v[8 + 2 * i]     = __bfloat162float(h.x);
            v[8 + 2 * i + 1] = __bfloat162float(h.y);
        }
    }

    float vmax = v[0];
#pragma unroll
    for (int i = 1; i < 16; ++i) vmax = fmaxf(vmax, v[i]);
#pragma unroll
    for (int o = 16; o; o >>= 1) vmax = fmaxf(vmax, __shfl_xor_sync(0xffffffffu, vmax, o));
    if ((tid & 31) == 0) sh[tid >> 5] = vmax;
    __syncthreads();
    const float rmax = fmaxf(fmaxf(fmaxf(sh[0], sh[1]), fmaxf(sh[2], sh[3])),
                             fmaxf(fmaxf(sh[4], sh[5]), fmaxf(sh[6], sh[7])));
    __syncthreads();

    float es = 0.f, e2 = 0.f;
#pragma unroll
    for (int i = 0; i < 16; ++i) {
        float e = __expf((v[i] - rmax) * inv_d);
        v[i] = e;
        es += e;
        e2 = fmaf(e, e, e2);
    }
#pragma unroll
    for (int o = 16; o; o >>= 1) {
        es += __shfl_xor_sync(0xffffffffu, es, o);
        e2 += __shfl_xor_sync(0xffffffffu, e2, o);
    }
    if ((tid & 31) == 0) { sh[tid >> 5] = es; sh[8 + (tid >> 5)] = e2; }
    __syncthreads();
    const float tes = sh[0] + sh[1] + sh[2] + sh[3] + sh[4] + sh[5] + sh[6] + sh[7];
    const float te2 = sh[8] + sh[9] + sh[10] + sh[11] + sh[12] + sh[13] + sh[14] + sh[15];

    const float inv = 1.f / tes;
    const float rn  = fmaxf(sqrtf(te2) * inv, MIN_NORM);
    const float sc  = sqrtf(c[0]);
    const float t   = fminf(tanhf(sc * rn), 1.0f - PROJ_EPS);
    const float scale = (t / (sc * rn)) * inv;

    float4* o = (float4*)(out + (size_t)row * m) + tid * 4;
#pragma unroll
    for (int i = 0; i < 4; ++i)
        o[i] = make_float4(v[4 * i] * scale, v[4 * i + 1] * scale,
                           v[4 * i + 2] * scale, v[4 * i + 3] * scale);
}

// ---------------------------------------------------------------------------
// kernel_launch: inputs: query[n,d], context[m,d], W[d,d], c[1]
// ---------------------------------------------------------------------------
extern "C" void kernel_launch(void* const* d_in, const int* in_sizes, int n_in,
                              void* d_out, int out_size) {
    const float* query   = (const float*)d_in[0];
    const float* context = (const float*)d_in[1];
    const float* W       = (const float*)d_in[2];
    const float* c       = (const float*)d_in[3];

    const int d = (int)(sqrt((double)in_sizes[2]) + 0.5);
    const int n = in_sizes[0] / d;
    const int m = in_sizes[1] / d;

    __nv_bfloat16 *qs, *cs, *wb, *q2, *sco;
    cudaGetSymbolAddress((void**)&qs,  g_qs);
    cudaGetSymbolAddress((void**)&cs,  g_cs);
    cudaGetSymbolAddress((void**)&wb,  g_wb);
    cudaGetSymbolAddress((void**)&q2,  g_q2);
    cudaGetSymbolAddress((void**)&sco, g_scores);

    cudaFuncSetAttribute(gemm_bf16_kernel,
                         cudaFuncAttributeMaxDynamicSharedMemorySize, GSMEM);

    // K1/K2: hyperbolic row scaling -> bf16
    scale_rows_kernel<<<n, 256>>>(query, qs, c, d);
    scale_rows_kernel<<<m, 256>>>(context, cs, c, d);

    // K3: W -> bf16
    const int n4 = (d * d) / 4;
    convert_w_kernel<<<(n4 + 255) / 256, 256>>>((const float4*)W, (__nv_bfloat162*)wb, n4);

    // K4: q2[n,d] = qs @ wb^T
    gemm_bf16_kernel<<<dim3(d / BN, n / BM), 256, GSMEM>>>(qs, wb, q2, n, d, d);

    // K5: scores[n,m] = q2 @ cs^T (bf16 out; logits are scores/1024, bf16-safe)
    gemm_bf16_kernel<<<dim3(m / BN, n / BM), 256, GSMEM>>>(q2, cs, sco, n, m, d);

    // K6: softmax(scores/d) + expmap0/project -> out (fp32)
    softmax_proj_kernel<<<n, 256>>>(sco, (float*)d_out, c, m, 1.0f / (float)d);
}

// round 8
// speedup vs baseline: 1.5853x; 1.1162x over previous
#include <cuda_runtime.h>
#include <cuda_bf16.h>
#include <math.h>
#include <stdint.h>

// ============================================================================
// HypHawkes (legacy-HMMA path; tcgen05 rejected by compute_103 lowering).
//
//   K1/K2: row-scale query/context (fused expmap0+project scalar) -> bf16
//   K3:    W -> bf16
//   K4:    GEMM1 q2[n,d] = qs @ wb^T      (mma.sync bf16, bf16 out)
//   K5:    GEMM2 scores[n,m] = q2 @ cs^T  (mma.sync bf16, bf16 out)
//   K6:    row softmax(scores/d) + expmap0/project -> out (fp32)
//
// GEMM: CTA tile 128x128x64, 3-stage cp.async (96 KB smem -> 2 CTAs/SM,
// 16 warps/SM), 8 warps (2m x 4n), warp tile 64x32, ldmatrix.x4 fragments,
// XOR-swizzled smem (conflict-free for 16B cp.async writes and LDSM reads).
// ============================================================================

#define MAXN 4096
#define MAXD 1024

__device__ __nv_bfloat16 g_qs[MAXN * MAXD];
__device__ __nv_bfloat16 g_cs[MAXN * MAXD];
__device__ __nv_bfloat16 g_wb[MAXD * MAXD];
__device__ __nv_bfloat16 g_q2[MAXN * MAXD];
__device__ __nv_bfloat16 g_scores[(size_t)MAXN * MAXN];

#define MIN_NORM 1e-5f
#define PROJ_EPS 4e-3f

// ---------------------------------------------------------------------------
// helpers
// ---------------------------------------------------------------------------
__device__ __forceinline__ uint32_t smem_u32(const void* p) {
    uint32_t a;
    asm("{ .reg .u64 t; cvta.to.shared.u64 t, %1; cvt.u32.u64 %0, t; }"
        : "=r"(a) : "l"(p));
    return a;
}
__device__ __forceinline__ void cp16(uint32_t dst, const void* src) {
    asm volatile("cp.async.cg.shared.global [%0], [%1], 16;" :: "r"(dst), "l"(src));
}
#define CP_COMMIT() asm volatile("cp.async.commit_group;" ::: "memory")
#define CP_WAIT(N)  asm volatile("cp.async.wait_group %0;" :: "n"(N) : "memory")

__device__ __forceinline__ void ldsm_x4(uint32_t* r, uint32_t addr) {
    asm volatile("ldmatrix.sync.aligned.m8n8.x4.shared.b16 {%0,%1,%2,%3}, [%4];"
                 : "=r"(r[0]), "=r"(r[1]), "=r"(r[2]), "=r"(r[3]) : "r"(addr));
}
__device__ __forceinline__ void mma16816(float* c, const uint32_t* a, const uint32_t* b) {
    asm volatile(
        "mma.sync.aligned.m16n8k16.row.col.f32.bf16.bf16.f32 "
        "{%0,%1,%2,%3}, {%4,%5,%6,%7}, {%8,%9}, {%0,%1,%2,%3};\n"
        : "+f"(c[0]), "+f"(c[1]), "+f"(c[2]), "+f"(c[3])
        : "r"(a[0]), "r"(a[1]), "r"(a[2]), "r"(a[3]), "r"(b[0]), "r"(b[1]));
}

// ---------------------------------------------------------------------------
// K1/K2: per-row hyperbolic scale + fp32->bf16
// ---------------------------------------------------------------------------
__global__ __launch_bounds__(256)
void scale_rows_kernel(const float* __restrict__ in, __nv_bfloat16* __restrict__ out,
                       const float* __restrict__ c, int d) {
    __shared__ float sh[8];
    const int row = blockIdx.x;
    const float* r = in + (size_t)row * d;
    float ss = 0.f;
    for (int i = threadIdx.x; i < d; i += 256) { float v = r[i]; ss = fmaf(v, v, ss); }
#pragma unroll
    for (int o = 16; o; o >>= 1) ss += __shfl_xor_sync(0xffffffffu, ss, o);
    if ((threadIdx.x & 31) == 0) sh[threadIdx.x >> 5] = ss;
    __syncthreads();
    const float tot = sh[0] + sh[1] + sh[2] + sh[3] + sh[4] + sh[5] + sh[6] + sh[7];
    const float sc = sqrtf(c[0]);
    const float rn = fmaxf(sqrtf(tot), MIN_NORM);
    const float t  = fminf(tanhf(sc * rn), 1.0f - PROJ_EPS);
    const float scale = t / (sc * rn);
    __nv_bfloat16* o = out + (size_t)row * d;
    for (int i = threadIdx.x; i < d; i += 256) o[i] = __float2bfloat16(r[i] * scale);
}

// ---------------------------------------------------------------------------
// K3: fp32 -> bf16 convert
// ---------------------------------------------------------------------------
__global__ __launch_bounds__(256)
void convert_w_kernel(const float4* __restrict__ in, __nv_bfloat162* __restrict__ out,
                      int n4) {
    int i = blockIdx.x * blockDim.x + threadIdx.x;
    if (i < n4) {
        float4 v = in[i];
        out[2 * i]     = __floats2bfloat162_rn(v.x, v.y);
        out[2 * i + 1] = __floats2bfloat162_rn(v.z, v.w);
    }
}

// ---------------------------------------------------------------------------
// GEMM (TN): C[M,N] = A[M,K] @ B[N,K]^T, bf16 in, fp32 acc, bf16 out.
// CTA 128x128x64, 3 stages, 96 KB smem, 2 CTAs/SM.
// ---------------------------------------------------------------------------
#define BM 128
#define BN 128
#define BK 64
#define STG 3
#define A_ST (BM * BK * 2)            // 16384 B
#define B_ST (BN * BK * 2)            // 16384 B
#define B_BASE (STG * A_ST)           // 49152
#define GSMEM (B_BASE + STG * B_ST)   // 98304 = 96 KB

extern __shared__ __align__(1024) char dyn_smem[];

__global__ __launch_bounds__(256, 2)
void gemm_bf16_kernel(const __nv_bfloat16* __restrict__ A,
                      const __nv_bfloat16* __restrict__ B,
                      __nv_bfloat16* __restrict__ C, int M, int N, int K) {
    const uint32_t sb = smem_u32(dyn_smem);
    const int tid  = threadIdx.x;
    const int wid  = tid >> 5;
    const int lane = tid & 31;
    const int bm = blockIdx.y * BM;
    const int bn = blockIdx.x * BN;
    const int wm = (wid & 1) * 64;    // warp m offset (2 warps in m)
    const int wn = (wid >> 1) * 32;   // warp n offset (4 warps in n)
    const int NK = K / BK;

    float acc[4][4][4];
#pragma unroll
    for (int i = 0; i < 4; i++)
#pragma unroll
        for (int j = 0; j < 4; j++)
#pragma unroll
            for (int k = 0; k < 4; k++) acc[i][j][k] = 0.f;

    // cp.async staging: rows are 128B (64 bf16) = 8 x 16B chunks; swizzle
    // chunk ^= (row & 7). A and B each 1024 chunks -> 4 per thread.
    auto load_stage = [&](int j) {
        const int s = (j % STG);
        const uint32_t ab = sb + s * A_ST;
        const uint32_t bb = sb + B_BASE + s * B_ST;
        const __nv_bfloat16* Aj = A + (size_t)bm * K + (size_t)j * BK;
        const __nv_bfloat16* Bj = B + (size_t)bn * K + (size_t)j * BK;
#pragma unroll
        for (int i = 0; i < 4; ++i) {
            int cid = tid + 256 * i;
            int row = cid >> 3, seg = cid & 7;
            uint32_t off = (uint32_t)(row * 128) + (uint32_t)((seg ^ (row & 7)) * 16);
            cp16(ab + off, Aj + (size_t)row * K + seg * 8);
        }
#pragma unroll
        for (int i = 0; i < 4; ++i) {
            int cid = tid + 256 * i;
            int row = cid >> 3, seg = cid & 7;
            uint32_t off = (uint32_t)(row * 128) + (uint32_t)((seg ^ (row & 7)) * 16);
            cp16(bb + off, Bj + (size_t)row * K + seg * 8);
        }
    };

    // prologue: stages 0..1
#pragma unroll
    for (int j = 0; j < STG - 1; ++j) { load_stage(j); CP_COMMIT(); }

    // per-thread LDSM address components
    const int sub  = lane >> 3;   // 0..3
    const int trow = lane & 7;
    // A x4: (m0-7,k0-7),(m8-15,k0-7),(m0-7,k8-15),(m8-15,k8-15)
    const int a_row_l = wm + (sub & 1) * 8 + trow;
    const int a_kk    = (sub >> 1) * 8;
    // B x4: (n0-7,k0-7),(n0-7,k8-15),(n8-15,k0-7),(n8-15,k8-15)
    const int b_row_l = wn + (sub >> 1) * 8 + trow;
    const int b_kk    = (sub & 1) * 8;
    const uint32_t sw = (uint32_t)trow << 4;  // XOR swizzle on bytes [6:4]

    for (int kt = 0; kt < NK; ++kt) {
        CP_WAIT(1);
        __syncthreads();
        const int jn = kt + STG - 1;
        if (jn < NK) load_stage(jn);
        CP_COMMIT();

        const int s = kt % STG;
        const uint32_t abase = sb + s * A_ST;
        const uint32_t bbase = sb + B_BASE + s * B_ST;

#pragma unroll
        for (int ks = 0; ks < 4; ++ks) {
            const int k0 = ks * 16;
            uint32_t af[4][4], bf[2][4];
#pragma unroll
            for (int mi = 0; mi < 4; ++mi) {
                uint32_t col = (uint32_t)((k0 + a_kk) * 2) ^ sw;
                ldsm_x4(af[mi], abase + (uint32_t)((a_row_l + mi * 16) * 128) + col);
            }
#pragma unroll
            for (int pi = 0; pi < 2; ++pi) {
                uint32_t col = (uint32_t)((k0 + b_kk) * 2) ^ sw;
                ldsm_x4(bf[pi], bbase + (uint32_t)((b_row_l + pi * 16) * 128) + col);
            }
#pragma unroll
            for (int mi = 0; mi < 4; ++mi)
#pragma unroll
                for (int ni = 0; ni < 4; ++ni)
                    mma16816(acc[mi][ni], af[mi], &bf[ni >> 1][(ni & 1) * 2]);
        }
        // no trailing barrier: next iteration's top __syncthreads orders the
        // stage-s overwrite (load-then-compute ordering within an iteration)
    }

    // epilogue
    const int g  = lane >> 2;
    const int tg = lane & 3;
#pragma unroll
    for (int mi = 0; mi < 4; ++mi) {
        const int row = bm + wm + mi * 16 + g;
#pragma unroll
        for (int ni = 0; ni < 4; ++ni) {
            const int col = bn + wn + ni * 8 + tg * 2;
            *(__nv_bfloat162*)&C[(size_t)row * N + col] =
                __floats2bfloat162_rn(acc[mi][ni][0], acc[mi][ni][1]);
            *(__nv_bfloat162*)&C[(size_t)(row + 8) * N + col] =
                __floats2bfloat162_rn(acc[mi][ni][2], acc[mi][ni][3]);
        }
    }
}

// ---------------------------------------------------------------------------
// K6: row softmax(scores * inv_d) fused with expmap0+project (bf16 scores in).
// ---------------------------------------------------------------------------
__global__ __launch_bounds__(256)
void softmax_proj_kernel(const __nv_bfloat16* __restrict__ S, float* __restrict__ out,
                         const float* __restrict__ c, int m, float inv_d) {
    __shared__ float sh[16];
    const int row = blockIdx.x;
    const int tid = threadIdx.x;

    const uint4* sv = (const uint4*)(S + (size_t)row * m) + tid * 2;
    uint4 u0 = sv[0], u1 = sv[1];
    float v[16];
    {
        const uint32_t* w = (const uint32_t*)&u0;
#pragma unroll
        for (int i = 0; i < 4; ++i) {
            __nv_bfloat162 h = *(__nv_bfloat162*)&w[i];
            v[2 * i]     = __bfloat162float(h.x);
            v[2 * i + 1] = __bfloat162float(h.y);
        }
        const uint32_t* w2 = (const uint32_t*)&u1;
#pragma unroll
        for (int i = 0; i < 4; ++i) {
            __nv_bfloat162 h = *(__nv_bfloat162*)&w2[i];
            v[8 + 2 * i]     = __bfloat162float(h.x);
            v[8 + 2 * i + 1] = __bfloat162float(h.y);
        }
    }

    float vmax = v[0];
#pragma unroll
    for (int i = 1; i < 16; ++i) vmax = fmaxf(vmax, v[i]);
#pragma unroll
    for (int o = 16; o; o >>= 1) vmax = fmaxf(vmax, __shfl_xor_sync(0xffffffffu, vmax, o));
    if ((tid & 31) == 0) sh[tid >> 5] = vmax;
    __syncthreads();
    const float rmax = fmaxf(fmaxf(fmaxf(sh[0], sh[1]), fmaxf(sh[2], sh[3])),
                             fmaxf(fmaxf(sh[4], sh[5]), fmaxf(sh[6], sh[7])));
    __syncthreads();

    float es = 0.f, e2 = 0.f;
#pragma unroll
    for (int i = 0; i < 16; ++i) {
        float e = __expf((v[i] - rmax) * inv_d);
        v[i] = e;
        es += e;
        e2 = fmaf(e, e, e2);
    }
#pragma unroll
    for (int o = 16; o; o >>= 1) {
        es += __shfl_xor_sync(0xffffffffu, es, o);
        e2 += __shfl_xor_sync(0xffffffffu, e2, o);
    }
    if ((tid & 31) == 0) { sh[tid >> 5] = es; sh[8 + (tid >> 5)] = e2; }
    __syncthreads();
    const float tes = sh[0] + sh[1] + sh[2] + sh[3] + sh[4] + sh[5] + sh[6] + sh[7];
    const float te2 = sh[8] + sh[9] + sh[10] + sh[11] + sh[12] + sh[13] + sh[14] + sh[15];

    const float inv = 1.f / tes;
    const float rn  = fmaxf(sqrtf(te2) * inv, MIN_NORM);
    const float sc  = sqrtf(c[0]);
    const float t   = fminf(tanhf(sc * rn), 1.0f - PROJ_EPS);
    const float scale = (t / (sc * rn)) * inv;

    float4* o = (float4*)(out + (size_t)row * m) + tid * 4;
#pragma unroll
    for (int i = 0; i < 4; ++i)
        o[i] = make_float4(v[4 * i] * scale, v[4 * i + 1] * scale,
                           v[4 * i + 2] * scale, v[4 * i + 3] * scale);
}

// ---------------------------------------------------------------------------
// kernel_launch: inputs: query[n,d], context[m,d], W[d,d], c[1]
// ---------------------------------------------------------------------------
extern "C" void kernel_launch(void* const* d_in, const int* in_sizes, int n_in,
                              void* d_out, int out_size) {
    const float* query   = (const float*)d_in[0];
    const float* context = (const float*)d_in[1];
    const float* W       = (const float*)d_in[2];
    const float* c       = (const float*)d_in[3];

    const int d = (int)(sqrt((double)in_sizes[2]) + 0.5);
    const int n = in_sizes[0] / d;
    const int m = in_sizes[1] / d;

    __nv_bfloat16 *qs, *cs, *wb, *q2, *sco;
    cudaGetSymbolAddress((void**)&qs,  g_qs);
    cudaGetSymbolAddress((void**)&cs,  g_cs);
    cudaGetSymbolAddress((void**)&wb,  g_wb);
    cudaGetSymbolAddress((void**)&q2,  g_q2);
    cudaGetSymbolAddress((void**)&sco, g_scores);

    cudaFuncSetAttribute(gemm_bf16_kernel,
                         cudaFuncAttributeMaxDynamicSharedMemorySize, GSMEM);

    // K1/K2: hyperbolic row scaling -> bf16
    scale_rows_kernel<<<n, 256>>>(query, qs, c, d);
    scale_rows_kernel<<<m, 256>>>(context, cs, c, d);

    // K3: W -> bf16
    const int n4 = (d * d) / 4;
    convert_w_kernel<<<(n4 + 255) / 256, 256>>>((const float4*)W, (__nv_bfloat162*)wb, n4);

    // K4: q2[n,d] = qs @ wb^T
    gemm_bf16_kernel<<<dim3(d / BN, n / BM), 256, GSMEM>>>(qs, wb, q2, n, d, d);

    // K5: scores[n,m] = q2 @ cs^T (bf16 out; logits are scores/1024, bf16-safe)
    gemm_bf16_kernel<<<dim3(m / BN, n / BM), 256, GSMEM>>>(q2, cs, sco, n, m, d);

    // K6: softmax(scores/d) + expmap0/project -> out (fp32)
    softmax_proj_kernel<<<n, 256>>>(sco, (float*)d_out, c, m, 1.0f / (float)d);
}